// round 16
// baseline (speedup 1.0000x reference)
#include <cuda_runtime.h>

// QConv2d: new_rho[b] = U2 @ rho[b] @ U2^T, U2 = uc[:,2:4] ⊗ ux ⊗ uy
// TWO-KERNEL split for wave-quantization balance (2.0 -> 1.75 batches/SM):
//  K1: grid B*4, CTA = (batch, quadrant (H=cl, h=cr)), 64 threads.
//      P1 load 64x64 quadrant -> smem; P2 per-thread row transform;
//      P3 per-thread column transform -> write M4 quadrant to scratch (coalesced).
//  K2: grid B*4, CTA = (batch, item-quarter), 256 threads.
//      P4: fused uc on both sides from scratch (L2-hot) + coalesced stores.

#define QRS 68                      // quadrant row stride (64 + 4 pad)
#define K1_SMEM_WORDS (64 * QRS + 128)
#define K1_SMEM_BYTES (K1_SMEM_WORDS * 4)

__device__ float g_scr[256 * 128 * 128];   // 16 MB M4 scratch (B=256)

__device__ __forceinline__ void transform64(float* __restrict__ d,
                                            const float4* __restrict__ Uy4,
                                            const float4* __restrict__ Ux4)
{
    // uy pass: 8 contiguous groups (x fixed)
#pragma unroll
    for (int x = 0; x < 8; x++) {
        float v[8];
#pragma unroll
        for (int k = 0; k < 8; k++) v[k] = d[x * 8 + k];
#pragma unroll
        for (int yo = 0; yo < 8; yo++) {
            const float4 ua = Uy4[yo * 2], ub = Uy4[yo * 2 + 1];
            float a =      ua.x * v[0];
            a = fmaf(ua.y, v[1], a);
            a = fmaf(ua.z, v[2], a);
            a = fmaf(ua.w, v[3], a);
            a = fmaf(ub.x, v[4], a);
            a = fmaf(ub.y, v[5], a);
            a = fmaf(ub.z, v[6], a);
            a = fmaf(ub.w, v[7], a);
            d[x * 8 + yo] = a;
        }
    }
    // ux pass: stride-8 groups (y fixed)
#pragma unroll
    for (int y = 0; y < 8; y++) {
        float v[8];
#pragma unroll
        for (int k = 0; k < 8; k++) v[k] = d[k * 8 + y];
#pragma unroll
        for (int xo = 0; xo < 8; xo++) {
            const float4 ua = Ux4[xo * 2], ub = Ux4[xo * 2 + 1];
            float a =      ua.x * v[0];
            a = fmaf(ua.y, v[1], a);
            a = fmaf(ua.z, v[2], a);
            a = fmaf(ua.w, v[3], a);
            a = fmaf(ub.x, v[4], a);
            a = fmaf(ub.y, v[5], a);
            a = fmaf(ub.z, v[6], a);
            a = fmaf(ub.w, v[7], a);
            d[xo * 8 + y] = a;
        }
    }
}

// ---------------- K1: quadrant P1-P3 -> scratch ----------------
__global__ __launch_bounds__(64)
void qconv_k1(const float* __restrict__ rho,
              const float* __restrict__ gux,
              const float* __restrict__ guy)
{
    extern __shared__ float sm[];
    float* Aq = sm;                 // 64 x QRS quadrant tile
    float* sU = sm + 64 * QRS;      // [0:64) uy, [64:128) ux

    const int t = threadIdx.x;
    const int b = blockIdx.x >> 2;
    const int Q = blockIdx.x & 3;
    const int H = Q >> 1;           // left-channel (row) block
    const int h = Q & 1;            // right-channel (col) block

    // U init (2 each)
    sU[t]      = __ldg(guy + t);
    sU[64 + t] = __ldg(gux + t);

    // P1: load the 64x64 quadrant, coalesced float4
    {
        const float4* src = (const float4*)(rho + (long)b * 16384);
#pragma unroll
        for (int i = 0; i < 16; i++) {
            const int idx = t + i * 64;          // 0..1023 float4 of quadrant
            const int row = idx >> 4;            // 0..63
            const int f4  = idx & 15;
            const float4 v = __ldg(src + (H * 64 + row) * 32 + h * 16 + f4);
            *(float4*)(Aq + row * QRS + f4 * 4) = v;
        }
    }
    __syncthreads();

    const float4* Uy4 = (const float4*)sU;
    const float4* Ux4 = (const float4*)(sU + 64);

    // P2: right-side transform, one row per thread
    {
        float* base = Aq + t * QRS;
        float d[64];
#pragma unroll
        for (int i = 0; i < 16; i++) {
            const float4 v = *(const float4*)(base + 4 * i);
            d[4 * i] = v.x; d[4 * i + 1] = v.y; d[4 * i + 2] = v.z; d[4 * i + 3] = v.w;
        }
        transform64(d, Uy4, Ux4);
#pragma unroll
        for (int i = 0; i < 16; i++)
            *(float4*)(base + 4 * i) =
                make_float4(d[4 * i], d[4 * i + 1], d[4 * i + 2], d[4 * i + 3]);
    }
    __syncthreads();

    // P3: left-side transform, one column per thread; write M4 quadrant to scratch
    {
        float d[64];
#pragma unroll
        for (int i = 0; i < 64; i++) d[i] = Aq[i * QRS + t];   // lanes stride-1
        transform64(d, Uy4, Ux4);
        float* dst = g_scr + (long)b * 16384 + (H * 64) * 128 + h * 64 + t;
#pragma unroll
        for (int i = 0; i < 64; i++) dst[i * 128] = d[i];      // lanes contiguous
    }
}

// ---------------- K2: P4 fused channel expansion + stores ----------------
__global__ __launch_bounds__(256)
void qconv_k2(const float* __restrict__ guc,
              float* __restrict__ out)
{
    const int b  = blockIdx.x >> 2;
    const int qi = blockIdx.x & 3;
    const int item = qi * 256 + threadIdx.x;   // 0..1023
    const int irv = item & 15;                 // right pixel / 4
    const int il  = item >> 4;                 // left pixel, 0..63

    float wc[8];
#pragma unroll
    for (int i = 0; i < 8; i++)                // i = c'*2 + c
        wc[i] = __ldg(guc + (i >> 1) * 4 + (i & 1) + 2);

    const float4* M = (const float4*)(g_scr + (long)b * 16384);  // 32 f4/row
    const float4 m00 = __ldg(M + il * 32 + irv);
    const float4 m01 = __ldg(M + il * 32 + 16 + irv);
    const float4 m10 = __ldg(M + (64 + il) * 32 + irv);
    const float4 m11 = __ldg(M + (64 + il) * 32 + 16 + irv);

    float4* outb = (float4*)(out + (long)b * 65536);

#pragma unroll
    for (int cpr = 0; cpr < 4; cpr++) {
        const float w0 = wc[cpr * 2], w1 = wc[cpr * 2 + 1];
        float4 t0, t1;
        t0.x = fmaf(w1, m01.x, w0 * m00.x);
        t0.y = fmaf(w1, m01.y, w0 * m00.y);
        t0.z = fmaf(w1, m01.z, w0 * m00.z);
        t0.w = fmaf(w1, m01.w, w0 * m00.w);
        t1.x = fmaf(w1, m11.x, w0 * m10.x);
        t1.y = fmaf(w1, m11.y, w0 * m10.y);
        t1.z = fmaf(w1, m11.z, w0 * m10.z);
        t1.w = fmaf(w1, m11.w, w0 * m10.w);
#pragma unroll
        for (int cpl = 0; cpl < 4; cpl++) {
            const float v0 = wc[cpl * 2], v1 = wc[cpl * 2 + 1];
            float4 o;
            o.x = fmaf(v1, t1.x, v0 * t0.x);
            o.y = fmaf(v1, t1.y, v0 * t0.y);
            o.z = fmaf(v1, t1.z, v0 * t0.z);
            o.w = fmaf(v1, t1.w, v0 * t0.w);
            outb[(cpl * 64 + il) * 64 + cpr * 16 + irv] = o;
        }
    }
}

extern "C" void kernel_launch(void* const* d_in, const int* in_sizes, int n_in,
                              void* d_out, int out_size)
{
    const float* rho = (const float*)d_in[0];
    const float* ux  = (const float*)d_in[1];
    const float* uy  = (const float*)d_in[2];
    const float* uc  = (const float*)d_in[3];
    float* out = (float*)d_out;

    const int B = in_sizes[0] / 16384;

    qconv_k1<<<B * 4, 64, K1_SMEM_BYTES>>>(rho, ux, uy);
    qconv_k2<<<B * 4, 256>>>(uc, out);
}